// round 3
// baseline (speedup 1.0000x reference)
#include <cuda_runtime.h>
#include <cstdint>

// Problem constants
#define N_OBJ   384
#define IN_DIM  256
#define CLS_DIM 128
#define HID     512
#define OUT_DIM 256
#define NPAIR   (N_OBJ * N_OBJ)      // 147456
#define BN_EPS  1e-5f

// Scratch (static __device__ arrays — allocation-free per harness rules)
__device__ float g_H2[(size_t)NPAIR * HID];   // 302 MB: BN(LeakyReLU(h))
__device__ float g_P[N_OBJ * HID];            // feats @ W1[:, 0:256]^T + b1
__device__ float g_Q[N_OBJ * HID];            // feats @ W1[:, 256:512]^T

// ---------------------------------------------------------------------------
// Shared SGEMM tile core: BM=128, BN=128, BK=16, 256 threads, 8x8 per thread.
// A: [M, K] row-major (lda), B: [N, K] row-major (ldb)  -> computes A @ B^T tile.
// ---------------------------------------------------------------------------
__device__ __forceinline__ void sgemm_tile(
    const float* __restrict__ A, int lda,
    const float* __restrict__ B, int ldb,
    int K, float acc[8][8], float* As, float* Bs, int tid)
{
    const int tx = tid & 15;
    const int ty = tid >> 4;
    for (int kt = 0; kt < K; kt += 16) {
        // Load A tile: 128 rows x 16 k -> As[k][m] (transposed)
        #pragma unroll
        for (int f = tid; f < 512; f += 256) {
            int row = f >> 2;
            int kc  = (f & 3) << 2;
            float4 v = *reinterpret_cast<const float4*>(A + (size_t)row * lda + kt + kc);
            As[(kc + 0) * 128 + row] = v.x;
            As[(kc + 1) * 128 + row] = v.y;
            As[(kc + 2) * 128 + row] = v.z;
            As[(kc + 3) * 128 + row] = v.w;
        }
        // Load B tile: 128 rows x 16 k -> Bs[k][n]
        #pragma unroll
        for (int f = tid; f < 512; f += 256) {
            int row = f >> 2;
            int kc  = (f & 3) << 2;
            float4 v = *reinterpret_cast<const float4*>(B + (size_t)row * ldb + kt + kc);
            Bs[(kc + 0) * 128 + row] = v.x;
            Bs[(kc + 1) * 128 + row] = v.y;
            Bs[(kc + 2) * 128 + row] = v.z;
            Bs[(kc + 3) * 128 + row] = v.w;
        }
        __syncthreads();
        #pragma unroll
        for (int k = 0; k < 16; k++) {
            float4 a0 = *reinterpret_cast<const float4*>(As + k * 128 + ty * 8);
            float4 a1 = *reinterpret_cast<const float4*>(As + k * 128 + ty * 8 + 4);
            float4 b0 = *reinterpret_cast<const float4*>(Bs + k * 128 + tx * 8);
            float4 b1 = *reinterpret_cast<const float4*>(Bs + k * 128 + tx * 8 + 4);
            float a[8] = {a0.x, a0.y, a0.z, a0.w, a1.x, a1.y, a1.z, a1.w};
            float b[8] = {b0.x, b0.y, b0.z, b0.w, b1.x, b1.y, b1.z, b1.w};
            #pragma unroll
            for (int r = 0; r < 8; r++)
                #pragma unroll
                for (int c = 0; c < 8; c++)
                    acc[r][c] = fmaf(a[r], b[c], acc[r][c]);
        }
        __syncthreads();
    }
}

// ---------------------------------------------------------------------------
// Kernel 0: P[i,h] = feats[i,:] @ W1[h, 0:256] + b1[h]   (z=0)
//           Q[i,h] = feats[i,:] @ W1[h, 256:512]          (z=1)
// grid (3, 4, 2)
// ---------------------------------------------------------------------------
__global__ __launch_bounds__(256) void k_pq(
    const float* __restrict__ feats, const float* __restrict__ W1,
    const float* __restrict__ b1)
{
    __shared__ __align__(16) float As[16 * 128];
    __shared__ __align__(16) float Bs[16 * 128];
    float acc[8][8] = {};
    const int tid = threadIdx.x;
    const int z = blockIdx.z;
    const float* A = feats + (size_t)blockIdx.x * 128 * IN_DIM;
    const float* B = W1 + (size_t)blockIdx.y * 128 * 640 + z * 256;
    sgemm_tile(A, IN_DIM, B, 640, IN_DIM, acc, As, Bs, tid);

    const int tx = tid & 15, ty = tid >> 4;
    const int row0 = blockIdx.x * 128 + ty * 8;
    const int col0 = blockIdx.y * 128 + tx * 8;
    float* dst = z ? g_Q : g_P;
    #pragma unroll
    for (int r = 0; r < 8; r++) {
        float out[8];
        #pragma unroll
        for (int c = 0; c < 8; c++) {
            float add = z ? 0.f : b1[col0 + c];
            out[c] = acc[r][c] + add;
        }
        float4* d4 = reinterpret_cast<float4*>(dst + (size_t)(row0 + r) * HID + col0);
        d4[0] = make_float4(out[0], out[1], out[2], out[3]);
        d4[1] = make_float4(out[4], out[5], out[6], out[7]);
    }
}

// ---------------------------------------------------------------------------
// Kernel 1: H2 = BN(LeakyReLU(cls @ W1c^T + P[i] + Q[j]))
// A = cls [147456, 128], B = W1[:, 512:640] rows (ldb=640)
// grid (1152, 4)
// ---------------------------------------------------------------------------
__global__ __launch_bounds__(256) void k_gemm1(
    const float* __restrict__ cls, const float* __restrict__ W1,
    const float* __restrict__ gamma, const float* __restrict__ beta,
    const float* __restrict__ rm, const float* __restrict__ rv)
{
    __shared__ __align__(16) float As[16 * 128];
    __shared__ __align__(16) float Bs[16 * 128];
    float acc[8][8] = {};
    const int tid = threadIdx.x;
    const float* A = cls + (size_t)blockIdx.x * 128 * CLS_DIM;
    const float* B = W1 + (size_t)blockIdx.y * 128 * 640 + 512;
    sgemm_tile(A, CLS_DIM, B, 640, CLS_DIM, acc, As, Bs, tid);

    const int tx = tid & 15, ty = tid >> 4;
    const int row0 = blockIdx.x * 128 + ty * 8;
    const int col0 = blockIdx.y * 128 + tx * 8;

    float sc[8], sh[8];
    #pragma unroll
    for (int c = 0; c < 8; c++) {
        int n = col0 + c;
        float s = gamma[n] * rsqrtf(rv[n] + BN_EPS);
        sc[c] = s;
        sh[c] = beta[n] - rm[n] * s;
    }
    #pragma unroll
    for (int r = 0; r < 8; r++) {
        int p = row0 + r;
        int i = p / N_OBJ;
        int j = p - i * N_OBJ;
        const float* Pp = g_P + (size_t)i * HID + col0;
        const float* Qp = g_Q + (size_t)j * HID + col0;
        float out[8];
        #pragma unroll
        for (int c = 0; c < 8; c++) {
            float v = acc[r][c] + Pp[c] + Qp[c];
            v = (v >= 0.f) ? v : 0.01f * v;              // LeakyReLU(0.01)
            out[c] = fmaf(v, sc[c], sh[c]);               // BatchNorm (eval)
        }
        float4* d4 = reinterpret_cast<float4*>(g_H2 + (size_t)p * HID + col0);
        d4[0] = make_float4(out[0], out[1], out[2], out[3]);
        d4[1] = make_float4(out[4], out[5], out[6], out[7]);
    }
}

// ---------------------------------------------------------------------------
// Kernel 2: features_out = H2 @ W2^T + b2    -> d_out[0 : 147456*256]
// grid (1152, 2)
// ---------------------------------------------------------------------------
__global__ __launch_bounds__(256) void k_gemm2(
    const float* __restrict__ W2, const float* __restrict__ b2,
    float* __restrict__ outF)
{
    __shared__ __align__(16) float As[16 * 128];
    __shared__ __align__(16) float Bs[16 * 128];
    float acc[8][8] = {};
    const int tid = threadIdx.x;
    const float* A = g_H2 + (size_t)blockIdx.x * 128 * HID;
    const float* B = W2 + (size_t)blockIdx.y * 128 * HID;
    sgemm_tile(A, HID, B, HID, HID, acc, As, Bs, tid);

    const int tx = tid & 15, ty = tid >> 4;
    const int row0 = blockIdx.x * 128 + ty * 8;
    const int col0 = blockIdx.y * 128 + tx * 8;
    float bb[8];
    #pragma unroll
    for (int c = 0; c < 8; c++) bb[c] = b2[col0 + c];
    #pragma unroll
    for (int r = 0; r < 8; r++) {
        float out[8];
        #pragma unroll
        for (int c = 0; c < 8; c++) out[c] = acc[r][c] + bb[c];
        float4* d4 = reinterpret_cast<float4*>(outF + (size_t)(row0 + r) * OUT_DIM + col0);
        d4[0] = make_float4(out[0], out[1], out[2], out[3]);
        d4[1] = make_float4(out[4], out[5], out[6], out[7]);
    }
}

// ---------------------------------------------------------------------------
// Kernel 3: attention tail. One block per i (384 blocks, 256 threads).
// logits[j] = features[i,j,:] . Wa   (ba cancels in softmax)
// enhanced[i,o] = sum_j softmax(logits)[j] * features[i,j,o]
// ---------------------------------------------------------------------------
__global__ __launch_bounds__(256) void k_attn(
    const float* __restrict__ F, const float* __restrict__ Wa,
    float* __restrict__ enh)
{
    __shared__ float wa_s[256];
    __shared__ float logit[384];
    __shared__ float red[256];
    const int i = blockIdx.x;
    const int tid = threadIdx.x;
    wa_s[tid] = Wa[tid];
    __syncthreads();

    const int warp = tid >> 5, lane = tid & 31;
    const float* base = F + (size_t)i * N_OBJ * OUT_DIM;
    for (int j = warp; j < N_OBJ; j += 8) {
        const float* row = base + (size_t)j * OUT_DIM;
        float s = 0.f;
        #pragma unroll
        for (int c = 0; c < 8; c++)
            s = fmaf(row[lane + 32 * c], wa_s[lane + 32 * c], s);
        #pragma unroll
        for (int o = 16; o; o >>= 1) s += __shfl_xor_sync(0xffffffffu, s, o);
        if (lane == 0) logit[j] = s;
    }
    __syncthreads();

    // block max
    float m = -3.4e38f;
    for (int j = tid; j < N_OBJ; j += 256) m = fmaxf(m, logit[j]);
    red[tid] = m; __syncthreads();
    for (int s = 128; s > 0; s >>= 1) {
        if (tid < s) red[tid] = fmaxf(red[tid], red[tid + s]);
        __syncthreads();
    }
    const float mx = red[0];
    __syncthreads();

    // exp + block sum
    float ls = 0.f;
    for (int j = tid; j < N_OBJ; j += 256) {
        float e = expf(logit[j] - mx);
        logit[j] = e;
        ls += e;
    }
    red[tid] = ls; __syncthreads();
    for (int s = 128; s > 0; s >>= 1) {
        if (tid < s) red[tid] += red[tid + s];
        __syncthreads();
    }
    const float inv = 1.f / red[0];

    // weighted sum over j; thread = output channel o (coalesced)
    float acc = 0.f;
    const float* col = base + tid;
    #pragma unroll 8
    for (int j = 0; j < N_OBJ; j++)
        acc = fmaf(logit[j], col[(size_t)j * OUT_DIM], acc);
    enh[(size_t)i * OUT_DIM + tid] = acc * inv;
}

// ---------------------------------------------------------------------------
// Launch. Output layout (flattened tuple, in order):
//   [0]                 features_out  147456*256
//   [37748736]          enhanced      384*256
//   [37847040]          classes_embedding 384*384*128
// ---------------------------------------------------------------------------
extern "C" void kernel_launch(void* const* d_in, const int* in_sizes, int n_in,
                              void* d_out, int out_size)
{
    const float* feats = (const float*)d_in[0];
    const float* cls   = (const float*)d_in[1];
    const float* W1    = (const float*)d_in[2];
    const float* b1    = (const float*)d_in[3];
    const float* gamma = (const float*)d_in[4];
    const float* beta  = (const float*)d_in[5];
    const float* rm    = (const float*)d_in[6];
    const float* rv    = (const float*)d_in[7];
    const float* W2    = (const float*)d_in[8];
    const float* b2    = (const float*)d_in[9];
    const float* Wa    = (const float*)d_in[10];
    // d_in[11] = ba: cancels in softmax, unused

    float* out  = (float*)d_out;
    float* outF = out;
    float* outE = out + (size_t)NPAIR * OUT_DIM;
    float* outC = outE + (size_t)N_OBJ * OUT_DIM;

    k_pq<<<dim3(3, 4, 2), 256>>>(feats, W1, b1);
    k_gemm1<<<dim3(NPAIR / 128, HID / 128), 256>>>(cls, W1, gamma, beta, rm, rv);
    k_gemm2<<<dim3(NPAIR / 128, OUT_DIM / 128), 256>>>(W2, b2, outF);
    k_attn<<<N_OBJ, 256>>>(outF, Wa, outE);
    cudaMemcpyAsync(outC, cls, (size_t)N_OBJ * N_OBJ * CLS_DIM * sizeof(float),
                    cudaMemcpyDeviceToDevice);
}

// round 5
// speedup vs baseline: 2.1392x; 2.1392x over previous
#include <cuda_runtime.h>
#include <cuda_bf16.h>
#include <cstdint>

// ---------------------------------------------------------------------------
// Problem constants
// ---------------------------------------------------------------------------
#define N_OBJ   384
#define IN_DIM  256
#define CLS_DIM 128
#define HID     512
#define OUT_DIM 256
#define NPAIR   (N_OBJ * N_OBJ)      // 147456
#define BN_EPS  1e-5f

// Scratch (static __device__ arrays — allocation-free per harness rules)
__device__ float g_H2[(size_t)NPAIR * HID];   // 302 MB: BN(LeakyReLU(h))
__device__ float g_P[N_OBJ * HID];            // feats @ W1[:, 0:256]^T + b1
__device__ float g_Q[N_OBJ * HID];            // feats @ W1[:, 256:512]^T

// ---------------------------------------------------------------------------
// SMEM geometry for the MMA GEMMs (bf16 hi/lo split tiles, BK=32)
//   row stride 40 bf16 = 80 B (odd multiple of 16B -> ldmatrix conflict-free)
// ---------------------------------------------------------------------------
#define BK        32
#define SROW      80                 // bytes per smem row
#define SPLIT_OFF 10240              // 128 * 80 (hi -> lo)
#define B_OFF     20480              // A block -> B block
#define BUF_OFF   40960              // double-buffer stride
#define SM_TOT    81920              // 2 buffers

__device__ __forceinline__ uint32_t smem_u32(const void* p) {
    uint32_t a;
    asm("{ .reg .u64 t; cvta.to.shared.u64 t, %1; cvt.u32.u64 %0, t; }"
        : "=r"(a) : "l"(p));
    return a;
}

__device__ __forceinline__ void ldsm4(uint32_t* r, uint32_t addr) {
    asm volatile("ldmatrix.sync.aligned.m8n8.x4.shared.b16 {%0,%1,%2,%3}, [%4];"
        : "=r"(r[0]), "=r"(r[1]), "=r"(r[2]), "=r"(r[3]) : "r"(addr));
}

__device__ __forceinline__ void mma16816(float* c, const uint32_t* a, const uint32_t* b) {
    asm volatile(
        "mma.sync.aligned.m16n8k16.row.col.f32.bf16.bf16.f32 "
        "{%0,%1,%2,%3}, {%4,%5,%6,%7}, {%8,%9}, {%0,%1,%2,%3};"
        : "+f"(c[0]), "+f"(c[1]), "+f"(c[2]), "+f"(c[3])
        : "r"(a[0]), "r"(a[1]), "r"(a[2]), "r"(a[3]), "r"(b[0]), "r"(b[1]));
}

// Split two f32 into packed bf16 hi and bf16 lo (residual) words.
__device__ __forceinline__ void split2(float x, float y, uint32_t& hi, uint32_t& lo) {
    __nv_bfloat16 hx = __float2bfloat16(x), hy = __float2bfloat16(y);
    float lx = x - __bfloat162float(hx);
    float ly = y - __bfloat162float(hy);
    __nv_bfloat16 ex = __float2bfloat16(lx), ey = __float2bfloat16(ly);
    hi = (uint32_t)__bfloat16_as_ushort(hx) | ((uint32_t)__bfloat16_as_ushort(hy) << 16);
    lo = (uint32_t)__bfloat16_as_ushort(ex) | ((uint32_t)__bfloat16_as_ushort(ey) << 16);
}

// Load one [128 x 32] f32 chunk from global, split to bf16 hi/lo in smem.
// Optional write-through of the raw f32 (fused cls -> output copy).
__device__ __forceinline__ void ld_cv(
    const float* __restrict__ src, int ld, int kc,
    char* smbase, float* wt, int tid)
{
    #pragma unroll
    for (int u = 0; u < 4; ++u) {
        int lin = tid + 256 * u;           // 0..1023
        int row = lin >> 3;                // 0..127
        int c4  = (lin & 7) << 2;          // 0,4,..,28
        const float* p = src + (size_t)row * ld + kc + c4;
        float4 v = *reinterpret_cast<const float4*>(p);
        if (wt)
            *reinterpret_cast<float4*>(wt + (size_t)row * ld + kc + c4) = v;
        uint32_t h0, l0, h1, l1;
        split2(v.x, v.y, h0, l0);
        split2(v.z, v.w, h1, l1);
        char* d = smbase + row * SROW + c4 * 2;
        *reinterpret_cast<uint2*>(d)             = make_uint2(h0, h1);
        *reinterpret_cast<uint2*>(d + SPLIT_OFF) = make_uint2(l0, l1);
    }
}

// One BK=32 chunk of split-3 bf16 MMAs. Warp tile 64x32 (2M x 4N warps).
__device__ __forceinline__ void mma_chunk(
    uint32_t base, int lane, int wid, float acc[4][4][4])
{
    const int m0w = (wid & 1) * 64;
    const int n0w = (wid >> 1) * 32;
    const int arow = (lane & 7) + ((lane >> 3) & 1) * 8;
    const int acol = (lane >> 4) << 3;
    const int brow = ((lane >> 4) << 3) + (lane & 7);
    const int bcol = ((lane >> 3) & 1) << 3;

    #pragma unroll
    for (int ks = 0; ks < 2; ++ks) {
        const int kk = ks * 16;
        uint32_t Ah[4][4], Al[4][4], Bh[8], Bl[8];
        #pragma unroll
        for (int mt = 0; mt < 4; ++mt) {
            uint32_t ad = base + (uint32_t)(m0w + 16 * mt + arow) * SROW + (acol + kk) * 2;
            ldsm4(Ah[mt], ad);
            ldsm4(Al[mt], ad + SPLIT_OFF);
        }
        #pragma unroll
        for (int np = 0; np < 2; ++np) {
            uint32_t bd = base + B_OFF +
                (uint32_t)(n0w + 16 * np + brow) * SROW + (bcol + kk) * 2;
            ldsm4(&Bh[4 * np], bd);
            ldsm4(&Bl[4 * np], bd + SPLIT_OFF);
        }
        #pragma unroll
        for (int mt = 0; mt < 4; ++mt)
            #pragma unroll
            for (int nt = 0; nt < 4; ++nt) {
                mma16816(acc[mt][nt], Ah[mt], &Bh[2 * nt]);   // hi*hi
                mma16816(acc[mt][nt], Ah[mt], &Bl[2 * nt]);   // hi*lo
                mma16816(acc[mt][nt], Al[mt], &Bh[2 * nt]);   // lo*hi
            }
    }
}

// ---------------------------------------------------------------------------
// GEMM1: H2 = BN(LeakyReLU(cls @ W1c^T + P[i] + Q[j]))    grid (1152, 4)
// blockIdx.y==0 blocks also write their cls tile to output (fused memcpy).
// ---------------------------------------------------------------------------
__global__ __launch_bounds__(256) void k_gemm1(
    const float* __restrict__ cls, const float* __restrict__ W1,
    const float* __restrict__ gamma, const float* __restrict__ beta,
    const float* __restrict__ rm, const float* __restrict__ rv,
    float* __restrict__ outC)
{
    extern __shared__ char sm[];
    const uint32_t su = smem_u32(sm);
    const int tid = threadIdx.x, lane = tid & 31, wid = tid >> 5;
    const int m0 = blockIdx.x * 128, n0 = blockIdx.y * 128;

    const float* A = cls + (size_t)m0 * CLS_DIM;
    const float* B = W1 + (size_t)n0 * 640 + 512;
    float* Awt = (blockIdx.y == 0) ? outC + (size_t)m0 * CLS_DIM : nullptr;

    float acc[4][4][4] = {};
    ld_cv(A, CLS_DIM, 0, sm, Awt, tid);
    ld_cv(B, 640, 0, sm + B_OFF, nullptr, tid);
    __syncthreads();

    const int NC = CLS_DIM / BK;   // 4
    for (int c = 0; c < NC; ++c) {
        if (c + 1 < NC) {
            char* nb = sm + ((c + 1) & 1) * BUF_OFF;
            ld_cv(A, CLS_DIM, (c + 1) * BK, nb, Awt, tid);
            ld_cv(B, 640, (c + 1) * BK, nb + B_OFF, nullptr, tid);
        }
        mma_chunk(su + (c & 1) * BUF_OFF, lane, wid, acc);
        __syncthreads();
    }

    // Epilogue: +P[i]+Q[j], LeakyReLU, BN, store
    const int m0w = (wid & 1) * 64;
    const int n0w = (wid >> 1) * 32;
    float sc[4][2], sh[4][2];
    #pragma unroll
    for (int nt = 0; nt < 4; ++nt) {
        int n = n0 + n0w + 8 * nt + 2 * (lane & 3);
        #pragma unroll
        for (int e = 0; e < 2; ++e) {
            float s = gamma[n + e] * rsqrtf(rv[n + e] + BN_EPS);
            sc[nt][e] = s;
            sh[nt][e] = beta[n + e] - rm[n + e] * s;
        }
    }
    #pragma unroll
    for (int mt = 0; mt < 4; ++mt)
        #pragma unroll
        for (int rh = 0; rh < 2; ++rh) {
            int p = m0 + m0w + 16 * mt + (lane >> 2) + 8 * rh;
            int i = p / N_OBJ;
            int j = p - i * N_OBJ;
            const float* Pr = g_P + (size_t)i * HID;
            const float* Qr = g_Q + (size_t)j * HID;
            #pragma unroll
            for (int nt = 0; nt < 4; ++nt) {
                int n = n0 + n0w + 8 * nt + 2 * (lane & 3);
                float v0 = acc[mt][nt][2 * rh + 0] + Pr[n] + Qr[n];
                float v1 = acc[mt][nt][2 * rh + 1] + Pr[n + 1] + Qr[n + 1];
                v0 = (v0 >= 0.f) ? v0 : 0.01f * v0;
                v1 = (v1 >= 0.f) ? v1 : 0.01f * v1;
                float2 o;
                o.x = fmaf(v0, sc[nt][0], sh[nt][0]);
                o.y = fmaf(v1, sc[nt][1], sh[nt][1]);
                *reinterpret_cast<float2*>(g_H2 + (size_t)p * HID + n) = o;
            }
        }
}

// ---------------------------------------------------------------------------
// GEMM2: features_out = H2 @ W2^T + b2      grid (1152, 2)
// ---------------------------------------------------------------------------
__global__ __launch_bounds__(256) void k_gemm2(
    const float* __restrict__ W2, const float* __restrict__ b2,
    float* __restrict__ outF)
{
    extern __shared__ char sm[];
    const uint32_t su = smem_u32(sm);
    const int tid = threadIdx.x, lane = tid & 31, wid = tid >> 5;
    const int m0 = blockIdx.x * 128, n0 = blockIdx.y * 128;

    const float* A = g_H2 + (size_t)m0 * HID;
    const float* B = W2 + (size_t)n0 * HID;

    float acc[4][4][4] = {};
    ld_cv(A, HID, 0, sm, nullptr, tid);
    ld_cv(B, HID, 0, sm + B_OFF, nullptr, tid);
    __syncthreads();

    const int NC = HID / BK;   // 16
    for (int c = 0; c < NC; ++c) {
        if (c + 1 < NC) {
            char* nb = sm + ((c + 1) & 1) * BUF_OFF;
            ld_cv(A, HID, (c + 1) * BK, nb, nullptr, tid);
            ld_cv(B, HID, (c + 1) * BK, nb + B_OFF, nullptr, tid);
        }
        mma_chunk(su + (c & 1) * BUF_OFF, lane, wid, acc);
        __syncthreads();
    }

    const int m0w = (wid & 1) * 64;
    const int n0w = (wid >> 1) * 32;
    float bb[4][2];
    #pragma unroll
    for (int nt = 0; nt < 4; ++nt) {
        int n = n0 + n0w + 8 * nt + 2 * (lane & 3);
        bb[nt][0] = b2[n];
        bb[nt][1] = b2[n + 1];
    }
    #pragma unroll
    for (int mt = 0; mt < 4; ++mt)
        #pragma unroll
        for (int rh = 0; rh < 2; ++rh) {
            int p = m0 + m0w + 16 * mt + (lane >> 2) + 8 * rh;
            #pragma unroll
            for (int nt = 0; nt < 4; ++nt) {
                int n = n0 + n0w + 8 * nt + 2 * (lane & 3);
                float2 o;
                o.x = acc[mt][nt][2 * rh + 0] + bb[nt][0];
                o.y = acc[mt][nt][2 * rh + 1] + bb[nt][1];
                *reinterpret_cast<float2*>(outF + (size_t)p * OUT_DIM + n) = o;
            }
        }
}

// ---------------------------------------------------------------------------
// P/Q precompute: fp32 register-blocked SGEMM (tiny: 0.2 GFLOP)
// ---------------------------------------------------------------------------
__device__ __forceinline__ void sgemm_tile(
    const float* __restrict__ A, int lda,
    const float* __restrict__ B, int ldb,
    int K, float acc[8][8], float* As, float* Bs, int tid)
{
    const int tx = tid & 15;
    const int ty = tid >> 4;
    for (int kt = 0; kt < K; kt += 16) {
        #pragma unroll
        for (int f = tid; f < 512; f += 256) {
            int row = f >> 2, kc = (f & 3) << 2;
            float4 v = *reinterpret_cast<const float4*>(A + (size_t)row * lda + kt + kc);
            As[(kc + 0) * 128 + row] = v.x; As[(kc + 1) * 128 + row] = v.y;
            As[(kc + 2) * 128 + row] = v.z; As[(kc + 3) * 128 + row] = v.w;
        }
        #pragma unroll
        for (int f = tid; f < 512; f += 256) {
            int row = f >> 2, kc = (f & 3) << 2;
            float4 v = *reinterpret_cast<const float4*>(B + (size_t)row * ldb + kt + kc);
            Bs[(kc + 0) * 128 + row] = v.x; Bs[(kc + 1) * 128 + row] = v.y;
            Bs[(kc + 2) * 128 + row] = v.z; Bs[(kc + 3) * 128 + row] = v.w;
        }
        __syncthreads();
        #pragma unroll
        for (int k = 0; k < 16; k++) {
            float4 a0 = *reinterpret_cast<const float4*>(As + k * 128 + ty * 8);
            float4 a1 = *reinterpret_cast<const float4*>(As + k * 128 + ty * 8 + 4);
            float4 b0 = *reinterpret_cast<const float4*>(Bs + k * 128 + tx * 8);
            float4 b1 = *reinterpret_cast<const float4*>(Bs + k * 128 + tx * 8 + 4);
            float a[8] = {a0.x, a0.y, a0.z, a0.w, a1.x, a1.y, a1.z, a1.w};
            float b[8] = {b0.x, b0.y, b0.z, b0.w, b1.x, b1.y, b1.z, b1.w};
            #pragma unroll
            for (int r = 0; r < 8; r++)
                #pragma unroll
                for (int c = 0; c < 8; c++)
                    acc[r][c] = fmaf(a[r], b[c], acc[r][c]);
        }
        __syncthreads();
    }
}

__global__ __launch_bounds__(256) void k_pq(
    const float* __restrict__ feats, const float* __restrict__ W1,
    const float* __restrict__ b1)
{
    __shared__ __align__(16) float As[16 * 128];
    __shared__ __align__(16) float Bs[16 * 128];
    float acc[8][8] = {};
    const int tid = threadIdx.x;
    const int z = blockIdx.z;
    const float* A = feats + (size_t)blockIdx.x * 128 * IN_DIM;
    const float* B = W1 + (size_t)blockIdx.y * 128 * 640 + z * 256;
    sgemm_tile(A, IN_DIM, B, 640, IN_DIM, acc, As, Bs, tid);

    const int tx = tid & 15, ty = tid >> 4;
    const int row0 = blockIdx.x * 128 + ty * 8;
    const int col0 = blockIdx.y * 128 + tx * 8;
    float* dst = z ? g_Q : g_P;
    #pragma unroll
    for (int r = 0; r < 8; r++) {
        float out[8];
        #pragma unroll
        for (int c = 0; c < 8; c++) {
            float add = z ? 0.f : b1[col0 + c];
            out[c] = acc[r][c] + add;
        }
        float4* d4 = reinterpret_cast<float4*>(dst + (size_t)(row0 + r) * HID + col0);
        d4[0] = make_float4(out[0], out[1], out[2], out[3]);
        d4[1] = make_float4(out[4], out[5], out[6], out[7]);
    }
}

// ---------------------------------------------------------------------------
// Attention tail — single pass over F with online softmax. One block per i.
// ---------------------------------------------------------------------------
__global__ __launch_bounds__(256) void k_attn(
    const float* __restrict__ F, const float* __restrict__ Wa,
    float* __restrict__ enh)
{
    __shared__ float wa_s[256];
    __shared__ float warp_m[8], warp_s[8];
    __shared__ float warp_acc[8][256];
    const int i = blockIdx.x;
    const int tid = threadIdx.x;
    const int w = tid >> 5, lane = tid & 31;
    wa_s[tid] = Wa[tid];
    __syncthreads();

    float m = -3.4e38f, sum = 0.f;
    float acc[8] = {};
    const float* base = F + (size_t)i * N_OBJ * OUT_DIM;
    for (int j = w; j < N_OBJ; j += 8) {
        const float* row = base + (size_t)j * OUT_DIM;
        float v[8];
        float dot = 0.f;
        #pragma unroll
        for (int k = 0; k < 8; k++) {
            v[k] = row[lane + 32 * k];
            dot = fmaf(v[k], wa_s[lane + 32 * k], dot);
        }
        #pragma unroll
        for (int o = 16; o; o >>= 1) dot += __shfl_xor_sync(0xffffffffu, dot, o);
        float mn = fmaxf(m, dot);
        float scale = expf(m - mn);
        float e = expf(dot - mn);
        sum = sum * scale + e;
        #pragma unroll
        for (int k = 0; k < 8; k++) acc[k] = fmaf(acc[k], scale, e * v[k]);
        m = mn;
    }
    if (lane == 0) { warp_m[w] = m; warp_s[w] = sum; }
    #pragma unroll
    for (int k = 0; k < 8; k++) warp_acc[w][lane + 32 * k] = acc[k];
    __syncthreads();

    float M = warp_m[0];
    #pragma unroll
    for (int q = 1; q < 8; q++) M = fmaxf(M, warp_m[q]);
    float S = 0.f, Ao = 0.f;
    #pragma unroll
    for (int q = 0; q < 8; q++) {
        float scq = expf(warp_m[q] - M);
        S = fmaf(warp_s[q], scq, S);
        Ao = fmaf(warp_acc[q][tid], scq, Ao);
    }
    enh[(size_t)i * OUT_DIM + tid] = Ao / S;
}

// ---------------------------------------------------------------------------
// Launch. Output layout: features_out | enhanced | classes_embedding
// ---------------------------------------------------------------------------
extern "C" void kernel_launch(void* const* d_in, const int* in_sizes, int n_in,
                              void* d_out, int out_size)
{
    const float* feats = (const float*)d_in[0];
    const float* cls   = (const float*)d_in[1];
    const float* W1    = (const float*)d_in[2];
    const float* b1    = (const float*)d_in[3];
    const float* gamma = (const float*)d_in[4];
    const float* beta  = (const float*)d_in[5];
    const float* rm    = (const float*)d_in[6];
    const float* rv    = (const float*)d_in[7];
    const float* W2    = (const float*)d_in[8];
    const float* b2    = (const float*)d_in[9];
    const float* Wa    = (const float*)d_in[10];
    // d_in[11] = ba: constant softmax shift, cancels

    float* out  = (float*)d_out;
    float* outF = out;
    float* outE = out + (size_t)NPAIR * OUT_DIM;
    float* outC = outE + (size_t)N_OBJ * OUT_DIM;

    static bool attr_set = false;
    if (!attr_set) {
        cudaFuncSetAttribute(k_gemm1, cudaFuncAttributeMaxDynamicSharedMemorySize, SM_TOT);
        cudaFuncSetAttribute(k_gemm2, cudaFuncAttributeMaxDynamicSharedMemorySize, SM_TOT);
        attr_set = true;
    }

    k_pq<<<dim3(3, 4, 2), 256>>>(feats, W1, b1);
    k_gemm1<<<dim3(NPAIR / 128, HID / 128), 256, SM_TOT>>>(
        cls, W1, gamma, beta, rm, rv, outC);
    k_gemm2<<<dim3(NPAIR / 128, OUT_DIM / 128), 256, SM_TOT>>>(W2, b2, outF);
    k_attn<<<N_OBJ, 256>>>(outF, Wa, outE);
}